// round 3
// baseline (speedup 1.0000x reference)
#include <cuda_runtime.h>
#include <cstdint>

typedef unsigned long long ull;

#define NTHREADS 256
#define TILE_B   16
#define TILE_N   1024
#define KSTAGE   8
#define NSTAGES  32          // DFEAT / KSTAGE
#define DFEAT    256
#define GRAPHK   50

// shared memory layout (in floats)
#define SM_FS    0                               // Fs [256][16]  k-major
#define SM_AS    (DFEAT * TILE_B)                // As [2][8][1024] k-major
#define SM_STAGE (SM_AS + 2 * KSTAGE * TILE_N)   // stage [16][1024]
#define SM_VALS  (SM_STAGE + TILE_B * TILE_N)    // vals [16][52]
#define SM_LABS  (SM_VALS + TILE_B * 52)         // labs [16][52] (int)
#define SM_TOTAL (SM_LABS + TILE_B * 52)
#define SMEM_BYTES (SM_TOTAL * 4)

#define NEG_INF (-3.402823466e38f)
#define POS_INF ( 3.402823466e38f)
#define FULLMASK 0xffffffffu

__device__ __forceinline__ ull ffma2(ull a, ull b, ull c) {
    ull d;
    asm("fma.rn.f32x2 %0, %1, %2, %3;" : "=l"(d) : "l"(a), "l"(b), "l"(c));
    return d;
}
__device__ __forceinline__ ull packdup(float x) {
    ull d;
    asm("mov.b64 %0, {%1, %1};" : "=l"(d) : "f"(x));
    return d;
}

__global__ __launch_bounds__(NTHREADS, 1)
void knn_sim_kernel(const float* __restrict__ features,
                    const float* __restrict__ anchor,
                    const int*   __restrict__ labels,
                    const int*   __restrict__ anchor_label,
                    float*       __restrict__ out,
                    int B, int N)
{
    extern __shared__ float sm[];
    float* Fs    = sm + SM_FS;
    float* As    = sm + SM_AS;
    float* stg   = sm + SM_STAGE;
    float* vals  = sm + SM_VALS;
    int*   labs  = (int*)(sm + SM_LABS);

    const int tx   = threadIdx.x;
    const int lane = tx & 31;
    const int warp = tx >> 5;         // 0..7
    const int rg   = warp & 1;        // row group: rows 8*rg .. 8*rg+7
    const int cg   = warp >> 1;       // col group: cols 256*cg .. +255
    const int b0   = blockIdx.x * TILE_B;

    // ---- load features tile transposed: Fs[k][r] (k-major) ----
    for (int m = 0; m < TILE_B; m++) {
        int idx = tx + NTHREADS * m;           // 0..4095
        int r = idx & 15;
        int k = idx >> 4;
        Fs[k * TILE_B + r] = features[(size_t)(b0 + r) * DFEAT + k];
    }

    // ---- init top-k lists: warp w owns rows 2w, 2w+1 ----
    #pragma unroll
    for (int rr = 0; rr < 2; rr++) {
        int r = 2 * warp + rr;
        if (lane < GRAPHK)      { vals[r*52 + lane]      = NEG_INF; labs[r*52 + lane]      = -1; }
        if (lane + 32 < GRAPHK) { vals[r*52 + lane + 32] = NEG_INF; labs[r*52 + lane + 32] = -1; }
    }
    float minv[2]; int minpos[2];
    minv[0] = NEG_INF; minv[1] = NEG_INF;
    minpos[0] = 0;     minpos[1] = 0;

    const int NCHUNK = (N + TILE_N - 1) / TILE_N;
    const int TOT    = NCHUNK * NSTAGES;

    // ---- staging: LDG (transposing) one stage (8 k x 1024 n) into regs ----
    float4 ld[8];
    const float4 z4 = make_float4(0.f, 0.f, 0.f, 0.f);

    {   // prologue: stage 0 -> buf 0
        #pragma unroll
        for (int j = 0; j < 8; j++) {
            int id = tx + NTHREADS * j;       // 0..2047
            int n  = id & 1023;
            int q  = id >> 10;                // 0/1 : k-quad
            ld[j] = (n < N) ? *(const float4*)(anchor + (size_t)n * DFEAT + 4 * q) : z4;
        }
        #pragma unroll
        for (int j = 0; j < 8; j++) {
            int id = tx + NTHREADS * j;
            int n  = id & 1023;
            int q  = id >> 10;
            float* p = As + (4 * q) * TILE_N + n;
            p[0*TILE_N] = ld[j].x; p[1*TILE_N] = ld[j].y;
            p[2*TILE_N] = ld[j].z; p[3*TILE_N] = ld[j].w;
        }
    }

    ull acc[8][4];
    #pragma unroll
    for (int i = 0; i < 8; i++)
        #pragma unroll
        for (int jp = 0; jp < 4; jp++) acc[i][jp] = 0ull;

    for (int ss = 0; ss < TOT; ss++) {
        const int buf = ss & 1;
        const bool have_next = (ss + 1 < TOT);

        // ---- issue LDG for next stage (latency hidden under compute) ----
        if (have_next) {
            const int ns  = ss + 1;
            const int k0  = (ns & (NSTAGES - 1)) * KSTAGE;
            const int n0n = (ns >> 5) * TILE_N;
            #pragma unroll
            for (int j = 0; j < 8; j++) {
                int id = tx + NTHREADS * j;
                int n  = id & 1023;
                int q  = id >> 10;
                int gn = n0n + n;
                ld[j] = (gn < N) ? *(const float4*)(anchor + (size_t)gn * DFEAT + k0 + 4 * q) : z4;
            }
        }

        __syncthreads();   // As[buf] visible; all warps done with As[buf^1]

        // ---- compute: 8 k-steps, lane tile 8 rows x 8 cols (f32x2 packed) ----
        const float* A   = As + buf * (KSTAGE * TILE_N);
        const int    kg0 = (ss & (NSTAGES - 1)) * KSTAGE;
        #pragma unroll
        for (int k = 0; k < KSTAGE; k++) {
            const float* fp = Fs + (kg0 + k) * TILE_B + 8 * rg;
            float4 f0 = *(const float4*)(fp);
            float4 f1 = *(const float4*)(fp + 4);
            const float* ap = A + k * TILE_N + cg * 256 + 4 * lane;
            ulonglong2 a0 = *(const ulonglong2*)(ap);        // cols 4l..4l+3
            ulonglong2 a1 = *(const ulonglong2*)(ap + 128);  // cols 128+4l..

            #define ROWF(i, fs) { ull ff = packdup(fs); \
                acc[i][0] = ffma2(ff, a0.x, acc[i][0]); \
                acc[i][1] = ffma2(ff, a0.y, acc[i][1]); \
                acc[i][2] = ffma2(ff, a1.x, acc[i][2]); \
                acc[i][3] = ffma2(ff, a1.y, acc[i][3]); }
            ROWF(0, f0.x) ROWF(1, f0.y) ROWF(2, f0.z) ROWF(3, f0.w)
            ROWF(4, f1.x) ROWF(5, f1.y) ROWF(6, f1.z) ROWF(7, f1.w)
            #undef ROWF
        }

        // ---- store next stage into the other buffer ----
        if (have_next) {
            float* Aw = As + (buf ^ 1) * (KSTAGE * TILE_N);
            #pragma unroll
            for (int j = 0; j < 8; j++) {
                int id = tx + NTHREADS * j;
                int n  = id & 1023;
                int q  = id >> 10;
                float* p = Aw + (4 * q) * TILE_N + n;
                p[0*TILE_N] = ld[j].x; p[1*TILE_N] = ld[j].y;
                p[2*TILE_N] = ld[j].z; p[3*TILE_N] = ld[j].w;
            }
        }

        // ---- chunk epilogue: sims -> stage smem, then top-k update ----
        if ((ss & (NSTAGES - 1)) == (NSTAGES - 1)) {
            const int c  = ss >> 5;
            const int n0 = c * TILE_N;

            #pragma unroll
            for (int i = 0; i < 8; i++) {
                int r = 8 * rg + i;
                float* dst = stg + r * TILE_N + cg * 256 + 4 * lane;
                *(ulonglong2*)(dst)       = make_ulonglong2(acc[i][0], acc[i][1]);
                *(ulonglong2*)(dst + 128) = make_ulonglong2(acc[i][2], acc[i][3]);
                acc[i][0] = acc[i][1] = acc[i][2] = acc[i][3] = 0ull;
            }
            __syncthreads();

            int valid = N - n0; if (valid > TILE_N) valid = TILE_N;
            #pragma unroll
            for (int rr = 0; rr < 2; rr++) {
                const int r = 2 * warp + rr;
                const float* srow = stg + r * TILE_N;
                float mv = minv[rr]; int mp = minpos[rr];
                for (int base = 0; base < TILE_N; base += 32) {
                    int j = base + lane;
                    float v = srow[j];
                    bool cand = (j < valid) && (v > mv);
                    unsigned m = __ballot_sync(FULLMASK, cand);
                    while (m) {
                        int src = __ffs(m) - 1; m &= m - 1;
                        float vv = __shfl_sync(FULLMASK, v, src);
                        if (vv > mv) {
                            if (lane == 0) {
                                vals[r*52 + mp] = vv;
                                labs[r*52 + mp] = anchor_label[n0 + base + src];
                            }
                            __syncwarp();
                            float x = (lane < GRAPHK) ? vals[r*52 + lane] : POS_INF;
                            int   p = lane;
                            if (lane + 32 < GRAPHK) {
                                float x2 = vals[r*52 + lane + 32];
                                if (x2 < x) { x = x2; p = lane + 32; }
                            }
                            #pragma unroll
                            for (int off = 16; off; off >>= 1) {
                                float ox = __shfl_down_sync(FULLMASK, x, off);
                                int   op = __shfl_down_sync(FULLMASK, p, off);
                                if (ox < x) { x = ox; p = op; }
                            }
                            mv = __shfl_sync(FULLMASK, x, 0);
                            mp = __shfl_sync(FULLMASK, p, 0);
                        }
                    }
                }
                minv[rr] = mv; minpos[rr] = mp;
            }
            // next iteration's __syncthreads separates this from further writes
        }
    }

    // ---- finalize ----
    #pragma unroll
    for (int rr = 0; rr < 2; rr++) {
        const int r   = 2 * warp + rr;
        const int row = b0 + r;
        const int lbl = labels[row];
        float sv = 0.f; int cnt = 0;
        if (lane < GRAPHK)      { sv  = vals[r*52 + lane];      cnt  = (labs[r*52 + lane]      == lbl); }
        if (lane + 32 < GRAPHK) { sv += vals[r*52 + lane + 32]; cnt += (labs[r*52 + lane + 32] == lbl); }
        #pragma unroll
        for (int off = 16; off; off >>= 1) {
            sv  += __shfl_down_sync(FULLMASK, sv, off);
            cnt += __shfl_down_sync(FULLMASK, cnt, off);
        }
        if (lane == 0) {
            out[row]     = -(float)cnt * (1.0f / GRAPHK);   // loss
            out[B + row] = sv * (1.0f / GRAPHK);            // mean_sim
        }
    }
}

extern "C" void kernel_launch(void* const* d_in, const int* in_sizes, int n_in,
                              void* d_out, int out_size)
{
    const float* features     = (const float*)d_in[0];
    const float* anchor       = (const float*)d_in[1];
    const int*   labels       = (const int*)d_in[2];
    // d_in[3] = t_labels (unused by the reference)
    const int*   anchor_label = (const int*)d_in[4];
    float* out = (float*)d_out;

    const int B = in_sizes[2];   // 2048
    const int N = in_sizes[4];   // 50000

    cudaFuncSetAttribute(knn_sim_kernel,
                         cudaFuncAttributeMaxDynamicSharedMemorySize, SMEM_BYTES);

    dim3 grid(B / TILE_B);       // 128 CTAs
    dim3 block(NTHREADS);
    knn_sim_kernel<<<grid, block, SMEM_BYTES>>>(features, anchor, labels,
                                                anchor_label, out, B, N);
}

// round 5
// speedup vs baseline: 1.4026x; 1.4026x over previous
#include <cuda_runtime.h>
#include <cstdint>

typedef unsigned long long ull;

#define NTHREADS 512
#define TILE_B   16
#define TILE_N   512
#define KSTAGE   32          // floats per stage (128B per anchor row)
#define NKST     8           // 256 / 32 k-stages per chunk
#define DFEAT    256
#define GRAPHK   50

// shared memory layout (floats)
#define SM_FS    0                                 // Fs [256][16] k-major
#define SM_AS    (DFEAT * TILE_B)                  // As [2][512][32] n-major, swizzled
#define SM_STG   (SM_AS + 2 * TILE_N * KSTAGE)     // stg [16][512]
#define SM_VALS  (SM_STG + TILE_B * TILE_N)        // vals [16][52]
#define SM_LABS  (SM_VALS + TILE_B * 52)           // labs [16][52] int
#define SM_TOTAL (SM_LABS + TILE_B * 52)
#define SMEM_BYTES (SM_TOTAL * 4)

#define NEG_INF (-3.402823466e38f)
#define POS_INF ( 3.402823466e38f)
#define FULLMASK 0xffffffffu

__device__ __forceinline__ ull ffma2(ull a, ull b, ull c) {
    ull d;
    asm("fma.rn.f32x2 %0, %1, %2, %3;" : "=l"(d) : "l"(a), "l"(b), "l"(c));
    return d;
}
__device__ __forceinline__ ull packdup(float x) {
    ull d;
    asm("mov.b64 %0, {%1, %1};" : "=l"(d) : "f"(x));
    return d;
}
__device__ __forceinline__ void cpasync16(uint32_t dst, const void* src, int srcbytes) {
    asm volatile("cp.async.cg.shared.global [%0], [%1], 16, %2;"
                 :: "r"(dst), "l"(src), "r"(srcbytes));
}
__device__ __forceinline__ void cp_commit() {
    asm volatile("cp.async.commit_group;" ::: "memory");
}
template <int N> __device__ __forceinline__ void cp_wait() {
    asm volatile("cp.async.wait_group %0;" :: "n"(N) : "memory");
}

__global__ __launch_bounds__(NTHREADS, 1)
void knn_sim_kernel(const float* __restrict__ features,
                    const float* __restrict__ anchor,
                    const int*   __restrict__ labels,
                    const int*   __restrict__ anchor_label,
                    float*       __restrict__ out,
                    int B, int N)
{
    extern __shared__ float sm[];
    float* Fs   = sm + SM_FS;
    float* As   = sm + SM_AS;
    float* stg  = sm + SM_STG;
    float* vals = sm + SM_VALS;
    int*   labs = (int*)(sm + SM_LABS);

    uint32_t sm_base;
    asm("{ .reg .u64 t; cvta.to.shared.u64 t, %1; cvt.u32.u64 %0, t; }"
        : "=r"(sm_base) : "l"(sm));
    const uint32_t As_bytes = sm_base + SM_AS * 4;

    const int tx   = threadIdx.x;
    const int lane = tx & 31;
    const int warp = tx >> 5;                 // 0..15
    const int b0   = blockIdx.x * TILE_B;

    // ---- load features tile transposed: Fs[k][r] (coalesced LDG) ----
    for (int m = 0; m < 8; m++) {
        int idx = tx + NTHREADS * m;          // 0..4095
        int r = idx >> 8;                     // 0..15
        int k = idx & 255;                    // 0..255
        Fs[k * TILE_B + r] = features[(size_t)(b0 + r) * DFEAT + k];
    }

    // ---- init top-k: warp w owns row w ----
    {
        int r = warp;
        if (lane < GRAPHK)      { vals[r*52 + lane]      = NEG_INF; labs[r*52 + lane]      = -1; }
        if (lane + 32 < GRAPHK) { vals[r*52 + lane + 32] = NEG_INF; labs[r*52 + lane + 32] = -1; }
    }
    float minv = NEG_INF; int minpos = 0;

    const int NCHUNK = (N + TILE_N - 1) / TILE_N;
    const int TOT    = NCHUNK * NKST;

    // lane geometry for compute: 8 rows x 2 cols per lane
    const int rg8 = 8 * (lane >> 4);              // row base 0 or 8
    const int nc0 = warp * 32 + 2 * (lane & 15);  // local col 0
    const int nc1 = nc0 + 1;
    const int sw0 = nc0 & 7, sw1 = nc1 & 7;

    // ---- staging helper (8 x 16B cp.async per thread) ----
    // idx = tx + 512*j : n = idx>>3 (0..511), u = idx&7 (16B unit)
    auto issue_stage = [&](int ss, int buf) {
        const int kb = (ss & (NKST - 1)) * KSTAGE;
        const int n0 = (ss >> 3) * TILE_N;
        const uint32_t base = As_bytes + (uint32_t)buf * (TILE_N * KSTAGE * 4);
        #pragma unroll
        for (int j = 0; j < 8; j++) {
            int idx = tx + NTHREADS * j;
            int n = idx >> 3;
            int u = idx & 7;
            int gn = n0 + n;
            int ok = (gn < N);
            const float* src = anchor + (size_t)(ok ? gn : 0) * DFEAT + kb + 4 * u;
            uint32_t dst = base + (uint32_t)(n * 128 + 16 * (u ^ (n & 7)));
            cpasync16(dst, src, ok ? 16 : 0);
        }
        cp_commit();
    };

    issue_stage(0, 0);

    ull acc[4][2];
    #pragma unroll
    for (int p = 0; p < 4; p++) { acc[p][0] = 0ull; acc[p][1] = 0ull; }

    __syncthreads();   // Fs + topk init visible

    for (int ss = 0; ss < TOT; ss++) {
        const int buf = ss & 1;
        const bool have_next = (ss + 1 < TOT);

        if (have_next) {
            issue_stage(ss + 1, buf ^ 1);
            cp_wait<1>();
        } else {
            cp_wait<0>();
        }
        __syncthreads();   // stage ss data visible to all

        // ---- compute: 32 k-steps at k-base kg0 ----
        const int kg0 = (ss & (NKST - 1)) * KSTAGE;     // <<< FIX: feature k-base
        const float* A = As + buf * (TILE_N * KSTAGE);
        const float* a0b = A + nc0 * KSTAGE;
        const float* a1b = A + nc1 * KSTAGE;
        #pragma unroll
        for (int kq = 0; kq < 8; kq++) {
            float4 aq0 = *(const float4*)(a0b + 4 * (kq ^ sw0));
            float4 aq1 = *(const float4*)(a1b + 4 * (kq ^ sw1));
            const float* fbase = Fs + (kg0 + 4 * kq) * TILE_B + rg8;   // <<< FIX
            #pragma unroll
            for (int kk = 0; kk < 4; kk++) {
                ulonglong2 fl = *(const ulonglong2*)(fbase + kk * TILE_B);
                ulonglong2 fh = *(const ulonglong2*)(fbase + kk * TILE_B + 4);
                float s0 = (kk == 0) ? aq0.x : (kk == 1) ? aq0.y : (kk == 2) ? aq0.z : aq0.w;
                float s1 = (kk == 0) ? aq1.x : (kk == 1) ? aq1.y : (kk == 2) ? aq1.z : aq1.w;
                ull d0 = packdup(s0);
                ull d1 = packdup(s1);
                acc[0][0] = ffma2(fl.x, d0, acc[0][0]); acc[0][1] = ffma2(fl.x, d1, acc[0][1]);
                acc[1][0] = ffma2(fl.y, d0, acc[1][0]); acc[1][1] = ffma2(fl.y, d1, acc[1][1]);
                acc[2][0] = ffma2(fh.x, d0, acc[2][0]); acc[2][1] = ffma2(fh.x, d1, acc[2][1]);
                acc[3][0] = ffma2(fh.y, d0, acc[3][0]); acc[3][1] = ffma2(fh.y, d1, acc[3][1]);
            }
        }

        if ((ss & (NKST - 1)) != (NKST - 1)) {
            __syncthreads();   // all done with buf before it is re-staged next iter
        } else {
            // ---- chunk epilogue: dump sims, run top-k ----
            const int n0 = (ss >> 3) * TILE_N;
            #pragma unroll
            for (int p = 0; p < 4; p++) {
                #pragma unroll
                for (int c = 0; c < 2; c++) {
                    float2 v = *(float2*)&acc[p][c];
                    int col = (c == 0) ? nc0 : nc1;
                    stg[(rg8 + 2*p)     * TILE_N + col] = v.x;
                    stg[(rg8 + 2*p + 1) * TILE_N + col] = v.y;
                    acc[p][c] = 0ull;
                }
            }
            __syncthreads();   // stg complete + buf free

            int valid = N - n0; if (valid > TILE_N) valid = TILE_N;
            const int r = warp;
            const float* srow = stg + r * TILE_N;
            float mv = minv; int mp = minpos;
            for (int base = 0; base < TILE_N; base += 32) {
                int j = base + lane;
                float v = srow[j];
                bool cand = (j < valid) && (v > mv);
                unsigned m = __ballot_sync(FULLMASK, cand);
                while (m) {
                    int src = __ffs(m) - 1; m &= m - 1;
                    float vv = __shfl_sync(FULLMASK, v, src);
                    if (vv > mv) {
                        if (lane == 0) {
                            vals[r*52 + mp] = vv;
                            labs[r*52 + mp] = anchor_label[n0 + base + src];
                        }
                        __syncwarp();
                        float x = (lane < GRAPHK) ? vals[r*52 + lane] : POS_INF;
                        int   p = lane;
                        if (lane + 32 < GRAPHK) {
                            float x2 = vals[r*52 + lane + 32];
                            if (x2 < x) { x = x2; p = lane + 32; }
                        }
                        #pragma unroll
                        for (int off = 16; off; off >>= 1) {
                            float ox = __shfl_down_sync(FULLMASK, x, off);
                            int   op = __shfl_down_sync(FULLMASK, p, off);
                            if (ox < x) { x = ox; p = op; }
                        }
                        mv = __shfl_sync(FULLMASK, x, 0);
                        mp = __shfl_sync(FULLMASK, p, 0);
                    }
                }
            }
            minv = mv; minpos = mp;
            // next iter's issue targets As (not stg); the post-wait
            // __syncthreads aligns everyone before compute.
        }
    }

    // ---- finalize: warp w -> row b0 + w ----
    {
        const int r   = warp;
        const int row = b0 + r;
        const int lbl = labels[row];
        float sv = 0.f; int cnt = 0;
        if (lane < GRAPHK)      { sv  = vals[r*52 + lane];      cnt  = (labs[r*52 + lane]      == lbl); }
        if (lane + 32 < GRAPHK) { sv += vals[r*52 + lane + 32]; cnt += (labs[r*52 + lane + 32] == lbl); }
        #pragma unroll
        for (int off = 16; off; off >>= 1) {
            sv  += __shfl_down_sync(FULLMASK, sv, off);
            cnt += __shfl_down_sync(FULLMASK, cnt, off);
        }
        if (lane == 0) {
            out[row]     = -(float)cnt * (1.0f / GRAPHK);   // loss
            out[B + row] = sv * (1.0f / GRAPHK);            // mean_sim
        }
    }
}

extern "C" void kernel_launch(void* const* d_in, const int* in_sizes, int n_in,
                              void* d_out, int out_size)
{
    const float* features     = (const float*)d_in[0];
    const float* anchor       = (const float*)d_in[1];
    const int*   labels       = (const int*)d_in[2];
    // d_in[3] = t_labels (unused by the reference)
    const int*   anchor_label = (const int*)d_in[4];
    float* out = (float*)d_out;

    const int B = in_sizes[2];   // 2048
    const int N = in_sizes[4];   // 50000

    cudaFuncSetAttribute(knn_sim_kernel,
                         cudaFuncAttributeMaxDynamicSharedMemorySize, SMEM_BYTES);

    dim3 grid(B / TILE_B);       // 128 CTAs
    dim3 block(NTHREADS);
    knn_sim_kernel<<<grid, block, SMEM_BYTES>>>(features, anchor, labels,
                                                anchor_label, out, B, N);
}

// round 6
// speedup vs baseline: 1.8600x; 1.3261x over previous
#include <cuda_runtime.h>
#include <cstdint>

typedef unsigned long long ull;

#define NTHREADS 512
#define TILE_B   32
#define TILE_N   512
#define KSTAGE   16          // floats per stage per anchor row (64B)
#define NKST     16          // 256/16 k-slots per chunk
#define RING     3
#define DFEAT    256
#define GRAPHK   50
#define BTOT     2048

// shared memory layout (floats)
#define SM_FS    0                                  // Fs [256][32] k-major
#define SM_AS    (DFEAT * TILE_B)                   // As ring [3][512][16]
#define SM_STG   (SM_AS + RING * TILE_N * KSTAGE)   // stg [32][512]
#define SM_VALS  (SM_STG + TILE_B * TILE_N)         // vals [32][52]
#define SM_LABS  (SM_VALS + TILE_B * 52)            // meta [32][52]
#define SM_TOTAL (SM_LABS + TILE_B * 52)
#define SMEM_BYTES (SM_TOTAL * 4)                   // ~210 KB

#define NEG_INF (-3.402823466e38f)
#define POS_INF ( 3.402823466e38f)
#define FULLMASK 0xffffffffu

__device__ float    g_svals[2][BTOT][GRAPHK];
__device__ unsigned g_smeta[2][BTOT][GRAPHK];

__device__ __forceinline__ ull ffma2(ull a, ull b, ull c) {
    ull d;
    asm("fma.rn.f32x2 %0, %1, %2, %3;" : "=l"(d) : "l"(a), "l"(b), "l"(c));
    return d;
}
__device__ __forceinline__ ull packdup(float x) {
    ull d;
    asm("mov.b64 %0, {%1, %1};" : "=l"(d) : "f"(x));
    return d;
}
__device__ __forceinline__ void cpasync16(uint32_t dst, const void* src, int srcbytes) {
    asm volatile("cp.async.cg.shared.global [%0], [%1], 16, %2;"
                 :: "r"(dst), "l"(src), "r"(srcbytes));
}
__device__ __forceinline__ void cp_commit() {
    asm volatile("cp.async.commit_group;" ::: "memory");
}
template <int N> __device__ __forceinline__ void cp_wait() {
    asm volatile("cp.async.wait_group %0;" :: "n"(N) : "memory");
}

__global__ __launch_bounds__(NTHREADS, 1)
void knn_sim_main(const float* __restrict__ features,
                  const float* __restrict__ anchor,
                  const int*   __restrict__ anchor_label,
                  int B, int N)
{
    extern __shared__ float sm[];
    float*    Fs   = sm + SM_FS;
    float*    As   = sm + SM_AS;
    float*    stg  = sm + SM_STG;
    float*    vals = sm + SM_VALS;
    unsigned* labs = (unsigned*)(sm + SM_LABS);

    uint32_t sm_base;
    asm("{ .reg .u64 t; cvta.to.shared.u64 t, %1; cvt.u32.u64 %0, t; }"
        : "=r"(sm_base) : "l"(sm));
    const uint32_t As_bytes = sm_base + SM_AS * 4;

    const int tx   = threadIdx.x;
    const int lane = tx & 31;
    const int warp = tx >> 5;                // 0..15
    const int half = blockIdx.x & 1;
    const int bt   = blockIdx.x >> 1;        // 0..63
    const int b0   = bt * TILE_B;

    const int Nh0     = (N + 1) >> 1;
    const int n_begin = half ? Nh0 : 0;
    const int n_end   = half ? N   : Nh0;
    const int Nh      = n_end - n_begin;

    // ---- features tile transposed: Fs[k][r] (r = 0..31) ----
    for (int m = 0; m < 16; m++) {
        int idx = tx + NTHREADS * m;         // 0..8191
        int r = idx >> 8;                    // 0..31
        int k = idx & 255;
        Fs[k * TILE_B + r] = features[(size_t)(b0 + r) * DFEAT + k];
    }

    // ---- top-k init: warp w owns rows 2w, 2w+1 ----
    #pragma unroll
    for (int rr = 0; rr < 2; rr++) {
        int r = 2 * warp + rr;
        if (lane < GRAPHK)      { vals[r*52 + lane]      = NEG_INF; labs[r*52 + lane]      = 0xFFFFFFFFu; }
        if (lane + 32 < GRAPHK) { vals[r*52 + lane + 32] = NEG_INF; labs[r*52 + lane + 32] = 0xFFFFFFFFu; }
    }
    float minv[2] = {NEG_INF, NEG_INF};
    int   minpos[2] = {0, 0};

    const int NCHUNK = (Nh + TILE_N - 1) / TILE_N;
    const int TOT    = NCHUNK * NKST;

    // compute geometry: lane tile 8 rows x 4 cols
    const int wr    = warp >> 3;                  // row group 0/1 (16 rows each)
    const int cg    = warp & 7;                   // col group (64 cols)
    const int rh    = lane >> 4;                  // 0/1 (8-row half)
    const int rbase = 16 * wr + 8 * rh;
    const int c0    = cg * 64 + (lane & 15);      // cols c0 + 16*cc, cc=0..3
    const int swc   = (c0 >> 1) & 3;              // a-unit swizzle key

    // ---- staging: 4 x 16B cp.async per thread per stage ----
    auto issue_stage = [&](int ss, int buf) {
        const int kb = (ss & (NKST - 1)) * KSTAGE;
        const int n0 = n_begin + (ss >> 4) * TILE_N;
        const uint32_t base = As_bytes + (uint32_t)buf * (TILE_N * KSTAGE * 4);
        #pragma unroll
        for (int j = 0; j < 4; j++) {
            int id = tx + NTHREADS * j;      // 0..2047
            int n  = id >> 2;                // 0..511
            int u  = id & 3;                 // k-quad
            int gn = n0 + n;
            int ok = (gn < n_end);
            const float* src = anchor + (size_t)(ok ? gn : 0) * DFEAT + kb + 4 * u;
            uint32_t dst = base + (uint32_t)(n * 64 + 16 * ((u ^ (n >> 1)) & 3));
            cpasync16(dst, src, ok ? 16 : 0);
        }
        cp_commit();
    };

    issue_stage(0, 0);
    issue_stage(1, 1);

    ull acc[4][4];
    #pragma unroll
    for (int p = 0; p < 4; p++)
        #pragma unroll
        for (int c = 0; c < 4; c++) acc[p][c] = 0ull;

    int buf = 0;
    for (int ss = 0; ss < TOT; ss++) {
        cp_wait<1>();       // my copies for stage ss complete
        __syncthreads();    // everyone's copies complete; buf (ss+2)%3 free

        if (ss + 2 < TOT) issue_stage(ss + 2, (buf + 2) % RING);

        // ---- compute: 16 k-steps ----
        const int kg0 = (ss & (NKST - 1)) * KSTAGE;
        const float* A = As + buf * (TILE_N * KSTAGE);
        #pragma unroll
        for (int kq = 0; kq < 4; kq++) {
            // hoist f operand: 4 kk x 8 rows (as 4 f32x2 each)
            ulonglong2 F[4][2];
            const float* fb = Fs + (kg0 + 4 * kq) * TILE_B + rbase;
            #pragma unroll
            for (int kk = 0; kk < 4; kk++) {
                F[kk][0] = *(const ulonglong2*)(fb + kk * TILE_B);
                F[kk][1] = *(const ulonglong2*)(fb + kk * TILE_B + 4);
            }
            const int uo = 4 * ((kq ^ swc) & 3);
            #pragma unroll
            for (int h = 0; h < 2; h++) {
                float4 ax = *(const float4*)(A + (c0 + 32*h)      * KSTAGE + uo);
                float4 ay = *(const float4*)(A + (c0 + 32*h + 16) * KSTAGE + uo);
                #pragma unroll
                for (int kk = 0; kk < 4; kk++) {
                    float sx = (kk==0)?ax.x:(kk==1)?ax.y:(kk==2)?ax.z:ax.w;
                    float sy = (kk==0)?ay.x:(kk==1)?ay.y:(kk==2)?ay.z:ay.w;
                    ull dx = packdup(sx);
                    ull dy = packdup(sy);
                    ull fl0 = F[kk][0].x, fl1 = F[kk][0].y;
                    ull fh0 = F[kk][1].x, fh1 = F[kk][1].y;
                    acc[0][2*h]   = ffma2(fl0, dx, acc[0][2*h]);
                    acc[1][2*h]   = ffma2(fl1, dx, acc[1][2*h]);
                    acc[2][2*h]   = ffma2(fh0, dx, acc[2][2*h]);
                    acc[3][2*h]   = ffma2(fh1, dx, acc[3][2*h]);
                    acc[0][2*h+1] = ffma2(fl0, dy, acc[0][2*h+1]);
                    acc[1][2*h+1] = ffma2(fl1, dy, acc[1][2*h+1]);
                    acc[2][2*h+1] = ffma2(fh0, dy, acc[2][2*h+1]);
                    acc[3][2*h+1] = ffma2(fh1, dy, acc[3][2*h+1]);
                }
            }
        }

        // ---- chunk epilogue every NKST stages ----
        if ((ss & (NKST - 1)) == (NKST - 1)) {
            const int n0 = n_begin + (ss >> 4) * TILE_N;
            #pragma unroll
            for (int p = 0; p < 4; p++) {
                #pragma unroll
                for (int c = 0; c < 4; c++) {
                    float2 v = *(float2*)&acc[p][c];
                    int row0 = rbase + 2 * p;
                    int col  = c0 + 16 * c;
                    stg[row0       * TILE_N + col] = v.x;
                    stg[(row0 + 1) * TILE_N + col] = v.y;
                    acc[p][c] = 0ull;
                }
            }
            __syncthreads();

            int valid = n_end - n0; if (valid > TILE_N) valid = TILE_N;
            #pragma unroll
            for (int rr = 0; rr < 2; rr++) {
                const int r = 2 * warp + rr;
                const float* srow = stg + r * TILE_N;
                float mv = minv[rr]; int mp = minpos[rr];
                for (int base = 0; base < TILE_N; base += 32) {
                    int j = base + lane;
                    float v = srow[j];
                    bool cand = (j < valid) && (v > mv);
                    unsigned m = __ballot_sync(FULLMASK, cand);
                    while (m) {
                        int src = __ffs(m) - 1; m &= m - 1;
                        float vv = __shfl_sync(FULLMASK, v, src);
                        if (vv > mv) {
                            if (lane == 0) {
                                int gidx = n0 + base + src;
                                vals[r*52 + mp] = vv;
                                labs[r*52 + mp] = (unsigned)gidx |
                                                  ((unsigned)anchor_label[gidx] << 16);
                            }
                            __syncwarp();
                            float x = (lane < GRAPHK) ? vals[r*52 + lane] : POS_INF;
                            int   p = lane;
                            if (lane + 32 < GRAPHK) {
                                float x2 = vals[r*52 + lane + 32];
                                if (x2 < x) { x = x2; p = lane + 32; }
                            }
                            #pragma unroll
                            for (int off = 16; off; off >>= 1) {
                                float ox = __shfl_down_sync(FULLMASK, x, off);
                                int   op = __shfl_down_sync(FULLMASK, p, off);
                                if (ox < x) { x = ox; p = op; }
                            }
                            mv = __shfl_sync(FULLMASK, x, 0);
                            mp = __shfl_sync(FULLMASK, p, 0);
                        }
                    }
                }
                minv[rr] = mv; minpos[rr] = mp;
            }
        }
        buf++; if (buf == RING) buf = 0;
    }

    // ---- dump per-half top-k candidates to scratch ----
    #pragma unroll
    for (int rr = 0; rr < 2; rr++) {
        const int r   = 2 * warp + rr;
        const int row = b0 + r;
        if (lane < GRAPHK) {
            g_svals[half][row][lane] = vals[r*52 + lane];
            g_smeta[half][row][lane] = labs[r*52 + lane];
        }
        if (lane + 32 < GRAPHK) {
            g_svals[half][row][lane + 32] = vals[r*52 + lane + 32];
            g_smeta[half][row][lane + 32] = labs[r*52 + lane + 32];
        }
    }
}

// ---- merge: exact top-50 of the 2x50 candidates per row ----
__global__ __launch_bounds__(256, 4)
void knn_sim_merge(const int* __restrict__ labels,
                   float* __restrict__ out, int B)
{
    __shared__ float    mv[8][2 * GRAPHK];
    __shared__ unsigned mm[8][2 * GRAPHK];

    const int lane = threadIdx.x & 31;
    const int w    = threadIdx.x >> 5;
    const int row  = blockIdx.x * 8 + w;
    if (row >= B) return;

    #pragma unroll
    for (int j = 0; j < 4; j++) {
        int c = lane + 32 * j;
        if (c < 2 * GRAPHK) {
            int h = c / GRAPHK, s = c % GRAPHK;
            mv[w][c] = g_svals[h][row][s];
            mm[w][c] = g_smeta[h][row][s];
        }
    }
    __syncwarp();

    const unsigned lbl = (unsigned)labels[row];
    float sum = 0.f; int cnt = 0;
    #pragma unroll
    for (int j = 0; j < 4; j++) {
        int c = lane + 32 * j;
        if (c < 2 * GRAPHK) {
            float    vi = mv[w][c];
            unsigned mi = mm[w][c];
            int rank = 0;
            for (int k = 0; k < 2 * GRAPHK; k++) {
                float    vk = mv[w][k];
                unsigned mk = mm[w][k];
                rank += (vk > vi) || (vk == vi && (mk & 0xFFFFu) < (mi & 0xFFFFu));
            }
            if (rank < GRAPHK) {
                sum += vi;
                cnt += ((mi >> 16) == lbl);
            }
        }
    }
    #pragma unroll
    for (int off = 16; off; off >>= 1) {
        sum += __shfl_down_sync(FULLMASK, sum, off);
        cnt += __shfl_down_sync(FULLMASK, cnt, off);
    }
    if (lane == 0) {
        out[row]     = -(float)cnt * (1.0f / GRAPHK);
        out[B + row] = sum * (1.0f / GRAPHK);
    }
}

extern "C" void kernel_launch(void* const* d_in, const int* in_sizes, int n_in,
                              void* d_out, int out_size)
{
    const float* features     = (const float*)d_in[0];
    const float* anchor       = (const float*)d_in[1];
    const int*   labels       = (const int*)d_in[2];
    // d_in[3] = t_labels (unused)
    const int*   anchor_label = (const int*)d_in[4];
    float* out = (float*)d_out;

    const int B = in_sizes[2];   // 2048
    const int N = in_sizes[4];   // 50000

    cudaFuncSetAttribute(knn_sim_main,
                         cudaFuncAttributeMaxDynamicSharedMemorySize, SMEM_BYTES);

    dim3 grid((B / TILE_B) * 2);   // 64 row-tiles x 2 N-halves = 128 CTAs
    knn_sim_main<<<grid, NTHREADS, SMEM_BYTES>>>(features, anchor, anchor_label, B, N);
    knn_sim_merge<<<(B + 7) / 8, 256>>>(labels, out, B);
}